// round 11
// baseline (speedup 1.0000x reference)
#include <cuda_runtime.h>
#include <cuda_bf16.h>
#include <cstdint>

#define D      128
#define DO2    256
#define NODES  50000
#define LN_EPS 1e-5f

#define CAP    64
#define SPILL_MAX 8192

#define GEMM_BLKS 782                   // 64-node tiles
#define SPMM_BLKS 6250                  // 8 rows per CTA (warp/row)

#define XROW_W 68
#define XTILE_W (64 * XROW_W)           // 4352 words per part
#define SMEM_TILE (2 * XTILE_W * 4)     // hi+lo tile: 34816 B

#define NKS    8

// Scratch
__device__ int      g_cnt[NODES];
__device__ int2     g_slots[NODES * CAP];
__device__ int4     g_spill[SPILL_MAX];
__device__ int      g_nspill;
__device__ float    g_support[NODES * D];
__device__ float    g_selfh[NODES * D];      // relu(h@Ws^T + b_self)
__device__ float    g_psum[NODES * 2];       // per-row partial sums (self half)
__device__ float    g_psq[NODES * 2];
// W fragments, LDG.128-packed: uint4[half][nt(16)][ks(8)][lane(32)]
__device__ uint4    g_Wfrag[2 * 16 * NKS * 32];

// ---------------------------------------------------------------------------
__device__ __forceinline__ uint32_t pack_bf2(__nv_bfloat16 lo, __nv_bfloat16 hi) {
    return (uint32_t)__bfloat16_as_ushort(hi) << 16 | (uint32_t)__bfloat16_as_ushort(lo);
}

__device__ __forceinline__ void mma_bf16(float& d0, float& d1, float& d2, float& d3,
                                         uint32_t a0, uint32_t a1, uint32_t a2, uint32_t a3,
                                         uint32_t b0, uint32_t b1) {
    asm volatile(
        "mma.sync.aligned.m16n8k16.row.col.f32.bf16.bf16.f32 "
        "{%0,%1,%2,%3}, {%4,%5,%6,%7}, {%8,%9}, {%0,%1,%2,%3};"
        : "+f"(d0), "+f"(d1), "+f"(d2), "+f"(d3)
        : "r"(a0), "r"(a1), "r"(a2), "r"(a3), "r"(b0), "r"(b1));
}

__device__ __forceinline__ void store_bf16_split(uint32_t* tHi, uint32_t* tLo,
                                                 int q4, float4 x) {
    __nv_bfloat16 hx = __float2bfloat16_rn(x.x);
    __nv_bfloat16 hy = __float2bfloat16_rn(x.y);
    __nv_bfloat16 hz = __float2bfloat16_rn(x.z);
    __nv_bfloat16 hw = __float2bfloat16_rn(x.w);
    __nv_bfloat16 lx = __float2bfloat16_rn(x.x - __bfloat162float(hx));
    __nv_bfloat16 ly = __float2bfloat16_rn(x.y - __bfloat162float(hy));
    __nv_bfloat16 lz = __float2bfloat16_rn(x.z - __bfloat162float(hz));
    __nv_bfloat16 lw = __float2bfloat16_rn(x.w - __bfloat162float(hw));
    tHi[2 * q4]     = pack_bf2(hx, hy);
    tHi[2 * q4 + 1] = pack_bf2(hz, hw);
    tLo[2 * q4]     = pack_bf2(lx, ly);
    tLo[2 * q4 + 1] = pack_bf2(lz, lw);
}

// MMA over 8 n-tiles for one half of the concat. acc[8][4].
__device__ __forceinline__ void mma_block(const uint32_t* __restrict__ sXtile,
                                          int mrow, int gr, int q, int lane,
                                          int ntb, int half,
                                          float acc[8][4]) {
    const uint32_t* aHi = sXtile + (mrow + gr) * XROW_W + q;
    const uint32_t* aLo = sXtile + XTILE_W + (mrow + gr) * XROW_W + q;
    const uint4* bBase = g_Wfrag + half * (16 * NKS * 32) + ntb * (NKS * 32) + lane;
    #pragma unroll
    for (int ks = 0; ks < NKS; ks++) {
        const int ko = ks * 8;
        uint32_t a0h = aHi[ko],     a1h = aHi[ko + 8 * XROW_W];
        uint32_t a2h = aHi[ko + 4], a3h = aHi[ko + 4 + 8 * XROW_W];
        uint32_t a0l = aLo[ko],     a1l = aLo[ko + 8 * XROW_W];
        uint32_t a2l = aLo[ko + 4], a3l = aLo[ko + 4 + 8 * XROW_W];
        const uint4* bp = bBase + ks * 32;
        #pragma unroll
        for (int ntl = 0; ntl < 8; ntl++) {
            uint4 b = __ldg(bp + ntl * (NKS * 32));
            mma_bf16(acc[ntl][0], acc[ntl][1], acc[ntl][2], acc[ntl][3],
                     a0h, a1h, a2h, a3h, b.x, b.y);
            mma_bf16(acc[ntl][0], acc[ntl][1], acc[ntl][2], acc[ntl][3],
                     a0h, a1h, a2h, a3h, b.z, b.w);
            mma_bf16(acc[ntl][0], acc[ntl][1], acc[ntl][2], acc[ntl][3],
                     a0l, a1l, a2l, a3l, b.x, b.y);
        }
    }
}

// ---------------------------------------------------------------------------
// prep: zero counters + build packed bf16-split W fragments.
__global__ void prep_kernel(const float* __restrict__ Ws,
                            const float* __restrict__ Wn) {
    int idx = blockIdx.x * blockDim.x + threadIdx.x;
    if (idx < NODES) g_cnt[idx] = 0;
    if (idx == 0) g_nspill = 0;
    if (idx < 2 * 16 * NKS * 32 * 4) {
        int w    = idx & 3;
        int lane = (idx >> 2) & 31;
        int ks   = (idx >> 7) & 7;
        int nt   = (idx >> 10) & 15;
        int half = (idx >> 14) & 1;
        int p    = w >> 1;
        int reg  = w & 1;
        int n    = nt * 8 + (lane >> 2);
        int k    = ks * 16 + reg * 8 + 2 * (lane & 3);
        const float* W = half ? Wn : Ws;
        float w0 = W[n * D + k];
        float w1 = W[n * D + k + 1];
        __nv_bfloat16 h0 = __float2bfloat16_rn(w0);
        __nv_bfloat16 h1 = __float2bfloat16_rn(w1);
        __nv_bfloat16 v0, v1;
        if (p == 0) { v0 = h0; v1 = h1; }
        else {
            v0 = __float2bfloat16_rn(w0 - __bfloat162float(h0));
            v1 = __float2bfloat16_rn(w1 - __bfloat162float(h1));
        }
        reinterpret_cast<uint32_t*>(g_Wfrag)[idx] = pack_bf2(v0, v1);
    }
}

// ---------------------------------------------------------------------------
__global__ void scatter_kernel(const int*  __restrict__ row,
                               const int*  __restrict__ col,
                               const float* __restrict__ val,
                               int E) {
    int e = blockIdx.x * blockDim.x + threadIdx.x;
    if (e >= E) return;
    int r = row[e];
    int slot = atomicAdd(&g_cnt[r], 1);
    if (slot < CAP) {
        g_slots[r * CAP + slot] = make_int2(col[e], __float_as_int(val[e]));
    } else {
        int sp = atomicAdd(&g_nspill, 1);
        if (sp < SPILL_MAX)
            g_spill[sp] = make_int4(r, col[e], __float_as_int(val[e]), 0);
    }
}

// ---------------------------------------------------------------------------
// K1: block-specialized. CTAs [0, GEMM_BLKS): self GEMM; rest: SpMM gather.
__global__ __launch_bounds__(256)
void k1_kernel(const float* __restrict__ h,
               const float* __restrict__ b_self) {
    extern __shared__ uint32_t sX[];
    const int tid  = threadIdx.x;
    const int wid  = tid >> 5;
    const int lane = tid & 31;

    if (blockIdx.x >= GEMM_BLKS) {
        // ---- SpMM role: one warp per destination row ----
        int gw = (blockIdx.x - GEMM_BLKS) * 8 + wid;
        if (gw >= NODES) return;
        int cnt0 = g_cnt[gw];
        bool over = cnt0 > CAP;
        int cnt = over ? CAP : cnt0;
        int beg = gw * CAP;
        int end = beg + cnt;

        float4 acc = make_float4(0.f, 0.f, 0.f, 0.f);
        int  e  = beg;
        int2 cv = (e < end) ? __ldg(&g_slots[e]) : make_int2(0, 0);
        while (e < end) {
            int2 cur = cv;
            if (e + 1 < end) cv = __ldg(&g_slots[e + 1]);
            float  v = __int_as_float(cur.y);
            float4 x = __ldg(reinterpret_cast<const float4*>(h + (size_t)cur.x * D) + lane);
            acc.x = fmaf(v, x.x, acc.x);
            acc.y = fmaf(v, x.y, acc.y);
            acc.z = fmaf(v, x.z, acc.z);
            acc.w = fmaf(v, x.w, acc.w);
            e++;
        }
        if (over) {
            int n = g_nspill; if (n > SPILL_MAX) n = SPILL_MAX;
            for (int i = 0; i < n; i++) {
                int4 s = g_spill[i];
                if (s.x == gw) {
                    float v = __int_as_float(s.z);
                    float4 x = __ldg(reinterpret_cast<const float4*>(h + (size_t)s.y * D) + lane);
                    acc.x = fmaf(v, x.x, acc.x);
                    acc.y = fmaf(v, x.y, acc.y);
                    acc.z = fmaf(v, x.z, acc.z);
                    acc.w = fmaf(v, x.w, acc.w);
                }
            }
        }
        reinterpret_cast<float4*>(g_support + (size_t)gw * D)[lane] = acc;
        return;
    }

    // ---- Self-GEMM role: 64 nodes, warp w: rows (w>>1)*16.., nt half (w&1) ----
    const int node0 = blockIdx.x * 64;
    for (int i = tid; i < 64 * 32; i += 256) {
        int row = i >> 5, q4 = i & 31;
        int gn = node0 + row;
        float4 x = (gn < NODES)
                 ? __ldg(reinterpret_cast<const float4*>(h + (size_t)gn * D) + q4)
                 : make_float4(0.f, 0.f, 0.f, 0.f);
        store_bf16_split(sX + row * XROW_W, sX + XTILE_W + row * XROW_W, q4, x);
    }
    __syncthreads();

    const int mrow = (wid >> 1) * 16;
    const int ntb  = (wid & 1) * 8;
    const int gr   = lane >> 2;
    const int q    = lane & 3;

    float acc[8][4];
    #pragma unroll
    for (int n = 0; n < 8; n++) acc[n][0] = acc[n][1] = acc[n][2] = acc[n][3] = 0.f;
    mma_block(sX, mrow, gr, q, lane, ntb, 0, acc);

    const float2* bb = reinterpret_cast<const float2*>(b_self);
    float sA = 0.f, qA = 0.f, sB = 0.f, qB = 0.f;
    #pragma unroll
    for (int n = 0; n < 8; n++) {
        float2 bv = __ldg(bb + (ntb + n) * 4 + q);
        float v0 = fmaxf(acc[n][0] + bv.x, 0.f);
        float v1 = fmaxf(acc[n][1] + bv.y, 0.f);
        float v2 = fmaxf(acc[n][2] + bv.x, 0.f);
        float v3 = fmaxf(acc[n][3] + bv.y, 0.f);
        acc[n][0] = v0; acc[n][1] = v1; acc[n][2] = v2; acc[n][3] = v3;
        sA += v0 + v1;  qA += v0 * v0 + v1 * v1;
        sB += v2 + v3;  qB += v2 * v2 + v3 * v3;
    }
    #pragma unroll
    for (int o = 1; o <= 2; o <<= 1) {
        sA += __shfl_xor_sync(0xffffffffu, sA, o);
        qA += __shfl_xor_sync(0xffffffffu, qA, o);
        sB += __shfl_xor_sync(0xffffffffu, sB, o);
        qB += __shfl_xor_sync(0xffffffffu, qB, o);
    }
    int gnA = node0 + mrow + gr;
    int gnB = gnA + 8;
    if (q == 0) {
        if (gnA < NODES) { g_psum[gnA * 2 + (wid & 1)] = sA; g_psq[gnA * 2 + (wid & 1)] = qA; }
        if (gnB < NODES) { g_psum[gnB * 2 + (wid & 1)] = sB; g_psq[gnB * 2 + (wid & 1)] = qB; }
    }
    #pragma unroll
    for (int n = 0; n < 8; n++) {
        int coff = (ntb + n) * 8 + 2 * q;
        if (gnA < NODES)
            *reinterpret_cast<float2*>(g_selfh + (size_t)gnA * D + coff)
                = make_float2(acc[n][0], acc[n][1]);
        if (gnB < NODES)
            *reinterpret_cast<float2*>(g_selfh + (size_t)gnB * D + coff)
                = make_float2(acc[n][2], acc[n][3]);
    }
}

// ---------------------------------------------------------------------------
// K2: neigh GEMM + full LayerNorm + output (both halves).
__global__ __launch_bounds__(256)
void k2_kernel(const float* __restrict__ b_neigh,
               const float* __restrict__ gamma,
               const float* __restrict__ beta,
               float* __restrict__ out) {
    extern __shared__ uint32_t sX[];
    __shared__ float sSumN[2][64];
    __shared__ float sSqN[2][64];
    __shared__ float sMu[64], sRs[64];

    const int tid   = threadIdx.x;
    const int wid   = tid >> 5;
    const int lane  = tid & 31;
    const int node0 = blockIdx.x * 64;

    for (int i = tid; i < 64 * 32; i += 256) {
        int row = i >> 5, q4 = i & 31;
        int gn = node0 + row;
        float4 x = (gn < NODES)
                 ? *(reinterpret_cast<const float4*>(g_support + (size_t)gn * D) + q4)
                 : make_float4(0.f, 0.f, 0.f, 0.f);
        store_bf16_split(sX + row * XROW_W, sX + XTILE_W + row * XROW_W, q4, x);
    }
    __syncthreads();

    const int mrow = (wid >> 1) * 16;
    const int ntb  = (wid & 1) * 8;
    const int gr   = lane >> 2;
    const int q    = lane & 3;

    float acc[8][4];
    #pragma unroll
    for (int n = 0; n < 8; n++) acc[n][0] = acc[n][1] = acc[n][2] = acc[n][3] = 0.f;
    mma_block(sX, mrow, gr, q, lane, ntb, 1, acc);

    const float2* bb = reinterpret_cast<const float2*>(b_neigh);
    float sA = 0.f, qA = 0.f, sB = 0.f, qB = 0.f;
    #pragma unroll
    for (int n = 0; n < 8; n++) {
        float2 bv = __ldg(bb + (ntb + n) * 4 + q);
        float v0 = fmaxf(acc[n][0] + bv.x, 0.f);
        float v1 = fmaxf(acc[n][1] + bv.y, 0.f);
        float v2 = fmaxf(acc[n][2] + bv.x, 0.f);
        float v3 = fmaxf(acc[n][3] + bv.y, 0.f);
        acc[n][0] = v0; acc[n][1] = v1; acc[n][2] = v2; acc[n][3] = v3;
        sA += v0 + v1;  qA += v0 * v0 + v1 * v1;
        sB += v2 + v3;  qB += v2 * v2 + v3 * v3;
    }
    #pragma unroll
    for (int o = 1; o <= 2; o <<= 1) {
        sA += __shfl_xor_sync(0xffffffffu, sA, o);
        qA += __shfl_xor_sync(0xffffffffu, qA, o);
        sB += __shfl_xor_sync(0xffffffffu, sB, o);
        qB += __shfl_xor_sync(0xffffffffu, qB, o);
    }
    if (q == 0) {
        sSumN[wid & 1][mrow + gr]     = sA;  sSqN[wid & 1][mrow + gr]     = qA;
        sSumN[wid & 1][mrow + gr + 8] = sB;  sSqN[wid & 1][mrow + gr + 8] = qB;
    }
    __syncthreads();

    if (tid < 64) {
        int gn = node0 + tid;
        float s  = sSumN[0][tid] + sSumN[1][tid];
        float sq = sSqN[0][tid] + sSqN[1][tid];
        if (gn < NODES) {
            s  += g_psum[gn * 2] + g_psum[gn * 2 + 1];
            sq += g_psq[gn * 2] + g_psq[gn * 2 + 1];
        }
        float mu  = s * (1.f / 256.f);
        float var = sq * (1.f / 256.f) - mu * mu;
        sMu[tid] = mu;
        sRs[tid] = rsqrtf(var + LN_EPS);
    }
    __syncthreads();

    // Write neigh half from registers
    {
        int gnA = node0 + mrow + gr;
        int gnB = gnA + 8;
        float muA = sMu[mrow + gr],     rsA = sRs[mrow + gr];
        float muB = sMu[mrow + gr + 8], rsB = sRs[mrow + gr + 8];
        const float2* gg = reinterpret_cast<const float2*>(gamma) + 64;
        const float2* ee = reinterpret_cast<const float2*>(beta)  + 64;
        #pragma unroll
        for (int n = 0; n < 8; n++) {
            float2 gv = __ldg(gg + (ntb + n) * 4 + q);
            float2 ev = __ldg(ee + (ntb + n) * 4 + q);
            int coff = 128 + (ntb + n) * 8 + 2 * q;
            if (gnA < NODES) {
                float2 o;
                o.x = (acc[n][0] - muA) * rsA * gv.x + ev.x;
                o.y = (acc[n][1] - muA) * rsA * gv.y + ev.y;
                *reinterpret_cast<float2*>(out + (size_t)gnA * DO2 + coff) = o;
            }
            if (gnB < NODES) {
                float2 o;
                o.x = (acc[n][2] - muB) * rsB * gv.x + ev.x;
                o.y = (acc[n][3] - muB) * rsB * gv.y + ev.y;
                *reinterpret_cast<float2*>(out + (size_t)gnB * DO2 + coff) = o;
            }
        }
    }

    // Write self half from g_selfh (coalesced float4)
    for (int i = tid; i < 64 * 32; i += 256) {
        int row = i >> 5, q4 = i & 31;
        int gn = node0 + row;
        if (gn < NODES) {
            float4 v = *(reinterpret_cast<const float4*>(g_selfh + (size_t)gn * D) + q4);
            float mu = sMu[row], rs = sRs[row];
            float4 gq = __ldg(reinterpret_cast<const float4*>(gamma) + q4);
            float4 eq = __ldg(reinterpret_cast<const float4*>(beta)  + q4);
            float4 o;
            o.x = (v.x - mu) * rs * gq.x + eq.x;
            o.y = (v.y - mu) * rs * gq.y + eq.y;
            o.z = (v.z - mu) * rs * gq.z + eq.z;
            o.w = (v.w - mu) * rs * gq.w + eq.w;
            reinterpret_cast<float4*>(out + (size_t)gn * DO2)[q4] = o;
        }
    }
}

// ---------------------------------------------------------------------------
extern "C" void kernel_launch(void* const* d_in, const int* in_sizes, int n_in,
                              void* d_out, int out_size) {
    const float* h        = (const float*)d_in[0];
    const int*   edge_row = (const int*)  d_in[1];
    const int*   edge_col = (const int*)  d_in[2];
    const float* edge_val = (const float*)d_in[3];
    const float* W_self   = (const float*)d_in[4];
    const float* b_self   = (const float*)d_in[5];
    const float* W_neigh  = (const float*)d_in[6];
    const float* b_neigh  = (const float*)d_in[7];
    const float* ln_gamma = (const float*)d_in[8];
    const float* ln_beta  = (const float*)d_in[9];
    float*       out      = (float*)d_out;

    const int E  = in_sizes[1];
    const int eb = (E + 255) / 256;

    static bool attr_done = false;
    if (!attr_done) {
        cudaFuncSetAttribute(k1_kernel,
                             cudaFuncAttributeMaxDynamicSharedMemorySize, SMEM_TILE);
        cudaFuncSetAttribute(k2_kernel,
                             cudaFuncAttributeMaxDynamicSharedMemorySize, SMEM_TILE);
        attr_done = true;
    }

    prep_kernel<<<196, 256>>>(W_self, W_neigh);
    scatter_kernel<<<eb, 256>>>(edge_row, edge_col, edge_val, E);
    k1_kernel<<<GEMM_BLKS + SPMM_BLKS, 256, SMEM_TILE>>>(h, b_self);
    k2_kernel<<<GEMM_BLKS, 256, SMEM_TILE>>>(b_neigh, ln_gamma, ln_beta, out);
}

// round 12
// speedup vs baseline: 1.1351x; 1.1351x over previous
#include <cuda_runtime.h>
#include <cuda_bf16.h>
#include <cstdint>

#define D      128
#define DO2    256
#define NODES  50000
#define LN_EPS 1e-5f

#define CAP    64
#define SPILL_MAX 8192

#define MTILE  64
#define GRID_G ((NODES + MTILE - 1) / MTILE) // 782

#define XROW_W 68
#define XTILE_W (64 * XROW_W)
#define SMEM_GEMM (4 * XTILE_W * 4)     // 69632 bytes

#define NKS    8

// Scratch
__device__ int      g_cnt[NODES];
__device__ int2     g_slots[NODES * CAP];
__device__ int4     g_spill[SPILL_MAX];
__device__ int      g_nspill;
// bf16 hi/lo packed feature tables: [node][64 words] (2 bf16 per word)
__device__ uint32_t g_hhi[NODES * 64];
__device__ uint32_t g_hlo[NODES * 64];
__device__ uint32_t g_shi[NODES * 64];
__device__ uint32_t g_slo[NODES * 64];
// W fragments, LDG.128-packed: uint4[half][nt(16)][ks(8)][lane(32)]
__device__ uint4    g_Wfrag[2 * 16 * NKS * 32];

// ---------------------------------------------------------------------------
__device__ __forceinline__ uint32_t pack_bf2(__nv_bfloat16 lo, __nv_bfloat16 hi) {
    return (uint32_t)__bfloat16_as_ushort(hi) << 16 | (uint32_t)__bfloat16_as_ushort(lo);
}

__device__ __forceinline__ void mma_bf16(float& d0, float& d1, float& d2, float& d3,
                                         uint32_t a0, uint32_t a1, uint32_t a2, uint32_t a3,
                                         uint32_t b0, uint32_t b1) {
    asm volatile(
        "mma.sync.aligned.m16n8k16.row.col.f32.bf16.bf16.f32 "
        "{%0,%1,%2,%3}, {%4,%5,%6,%7}, {%8,%9}, {%0,%1,%2,%3};"
        : "+f"(d0), "+f"(d1), "+f"(d2), "+f"(d3)
        : "r"(a0), "r"(a1), "r"(a2), "r"(a3), "r"(b0), "r"(b1));
}

// Convert float4 to (hi0,hi1) and (lo0,lo1) packed words
__device__ __forceinline__ void split_packs(float4 x, uint2& hi, uint2& lo) {
    __nv_bfloat16 hx = __float2bfloat16_rn(x.x);
    __nv_bfloat16 hy = __float2bfloat16_rn(x.y);
    __nv_bfloat16 hz = __float2bfloat16_rn(x.z);
    __nv_bfloat16 hw = __float2bfloat16_rn(x.w);
    __nv_bfloat16 lx = __float2bfloat16_rn(x.x - __bfloat162float(hx));
    __nv_bfloat16 ly = __float2bfloat16_rn(x.y - __bfloat162float(hy));
    __nv_bfloat16 lz = __float2bfloat16_rn(x.z - __bfloat162float(hz));
    __nv_bfloat16 lw = __float2bfloat16_rn(x.w - __bfloat162float(hw));
    hi.x = pack_bf2(hx, hy);  hi.y = pack_bf2(hz, hw);
    lo.x = pack_bf2(lx, ly);  lo.y = pack_bf2(lz, lw);
}

// ---------------------------------------------------------------------------
// prep: zero counters + W fragments + convert h to bf16 hi/lo tables.
__global__ void prep_kernel(const float* __restrict__ h,
                            const float* __restrict__ Ws,
                            const float* __restrict__ Wn) {
    int idx = blockIdx.x * blockDim.x + threadIdx.x;
    if (idx < NODES) g_cnt[idx] = 0;
    if (idx == 0) g_nspill = 0;
    if (idx < 2 * 16 * NKS * 32 * 4) {
        int w    = idx & 3;
        int lane = (idx >> 2) & 31;
        int ks   = (idx >> 7) & 7;
        int nt   = (idx >> 10) & 15;
        int half = (idx >> 14) & 1;
        int p    = w >> 1;
        int reg  = w & 1;
        int n    = nt * 8 + (lane >> 2);
        int k    = ks * 16 + reg * 8 + 2 * (lane & 3);
        const float* W = half ? Wn : Ws;
        float w0 = W[n * D + k];
        float w1 = W[n * D + k + 1];
        __nv_bfloat16 h0 = __float2bfloat16_rn(w0);
        __nv_bfloat16 h1 = __float2bfloat16_rn(w1);
        __nv_bfloat16 v0, v1;
        if (p == 0) { v0 = h0; v1 = h1; }
        else {
            v0 = __float2bfloat16_rn(w0 - __bfloat162float(h0));
            v1 = __float2bfloat16_rn(w1 - __bfloat162float(h1));
        }
        reinterpret_cast<uint32_t*>(g_Wfrag)[idx] = pack_bf2(v0, v1);
    }
    // h conversion: idx in [0, NODES*32), node = idx>>5, q4 = idx&31
    if (idx < NODES * 32) {
        int node = idx >> 5;
        int q4   = idx & 31;
        float4 x = __ldg(reinterpret_cast<const float4*>(h + (size_t)node * D) + q4);
        uint2 hi, lo;
        split_packs(x, hi, lo);
        reinterpret_cast<uint2*>(g_hhi)[node * 32 + q4] = hi;
        reinterpret_cast<uint2*>(g_hlo)[node * 32 + q4] = lo;
    }
}

// ---------------------------------------------------------------------------
__global__ void scatter_kernel(const int*  __restrict__ row,
                               const int*  __restrict__ col,
                               const float* __restrict__ val,
                               int E) {
    int e = blockIdx.x * blockDim.x + threadIdx.x;
    if (e >= E) return;
    int r = row[e];
    int slot = atomicAdd(&g_cnt[r], 1);
    if (slot < CAP) {
        g_slots[r * CAP + slot] = make_int2(col[e], __float_as_int(val[e]));
    } else {
        int sp = atomicAdd(&g_nspill, 1);
        if (sp < SPILL_MAX)
            g_spill[sp] = make_int4(r, col[e], __float_as_int(val[e]), 0);
    }
}

// ---------------------------------------------------------------------------
// Bucketed SpMM: one warp per row; writes bf16-split packed support.
// Spill edges folded inline (rare).
__global__ __launch_bounds__(256)
void spmm_kernel(const float* __restrict__ h) {
    int gw   = (blockIdx.x * blockDim.x + threadIdx.x) >> 5;
    int lane = threadIdx.x & 31;
    if (gw >= NODES) return;

    int cnt0 = g_cnt[gw];
    bool over = cnt0 > CAP;
    int cnt = over ? CAP : cnt0;
    int beg = gw * CAP;
    int end = beg + cnt;

    float4 acc = make_float4(0.f, 0.f, 0.f, 0.f);
    int  e  = beg;
    int2 cv = (e < end) ? __ldg(&g_slots[e]) : make_int2(0, 0);
    while (e < end) {
        int2 cur = cv;
        if (e + 1 < end) cv = __ldg(&g_slots[e + 1]);
        float  v = __int_as_float(cur.y);
        float4 x = __ldg(reinterpret_cast<const float4*>(h + (size_t)cur.x * D) + lane);
        acc.x = fmaf(v, x.x, acc.x);
        acc.y = fmaf(v, x.y, acc.y);
        acc.z = fmaf(v, x.z, acc.z);
        acc.w = fmaf(v, x.w, acc.w);
        e++;
    }
    if (over) {
        int n = g_nspill; if (n > SPILL_MAX) n = SPILL_MAX;
        for (int i = 0; i < n; i++) {
            int4 s = g_spill[i];
            if (s.x == gw) {
                float v = __int_as_float(s.z);
                float4 x = __ldg(reinterpret_cast<const float4*>(h + (size_t)s.y * D) + lane);
                acc.x = fmaf(v, x.x, acc.x);
                acc.y = fmaf(v, x.y, acc.y);
                acc.z = fmaf(v, x.z, acc.z);
                acc.w = fmaf(v, x.w, acc.w);
            }
        }
    }
    uint2 hi, lo;
    split_packs(acc, hi, lo);
    reinterpret_cast<uint2*>(g_shi)[gw * 32 + lane] = hi;
    reinterpret_cast<uint2*>(g_slo)[gw * 32 + lane] = lo;
}

// ---------------------------------------------------------------------------
// Tensor-core fused GEMM (bf16x3 split via mma.sync) + concat + ReLU + LN.
// Staging is now a pure copy from pre-converted tables.
__global__ __launch_bounds__(256)
void gemm_ln_tc_kernel(const float* __restrict__ b_self,
                       const float* __restrict__ b_neigh,
                       const float* __restrict__ gamma,
                       const float* __restrict__ beta,
                       float* __restrict__ out) {
    extern __shared__ uint32_t sX[];        // tiles: 0=h_hi 1=h_lo 2=s_hi 3=s_lo
    __shared__ float sSum[2][64];
    __shared__ float sSq[2][64];

    const int tid   = threadIdx.x;
    const int node0 = blockIdx.x * MTILE;

    // Stage: 4096 uint4 copies (tile(2) | row(6) | u4(4))
    #pragma unroll 4
    for (int i = tid; i < 4096; i += 256) {
        int tile = i >> 10;
        int rem  = i & 1023;
        int row  = rem >> 4;
        int u4   = rem & 15;
        int gn   = node0 + row;
        uint4 v = make_uint4(0u, 0u, 0u, 0u);
        if (gn < NODES) {
            const uint32_t* src = (tile == 0) ? g_hhi : (tile == 1) ? g_hlo
                                : (tile == 2) ? g_shi : g_slo;
            v = __ldg(reinterpret_cast<const uint4*>(src) + gn * 16 + u4);
        }
        *reinterpret_cast<uint4*>(sX + tile * XTILE_W + row * XROW_W + u4 * 4) = v;
    }
    __syncthreads();

    const int wid  = tid >> 5;
    const int lane = tid & 31;
    const int half = wid >> 2;
    const int mr   = (wid & 3) * 16;
    const int gr   = lane >> 2;
    const int q    = lane & 3;

    float acc[16][4];
    #pragma unroll
    for (int nt = 0; nt < 16; nt++)
        acc[nt][0] = acc[nt][1] = acc[nt][2] = acc[nt][3] = 0.f;

    const uint32_t* aHi = sX + (half * 2 + 0) * XTILE_W + (mr + gr) * XROW_W + q;
    const uint32_t* aLo = sX + (half * 2 + 1) * XTILE_W + (mr + gr) * XROW_W + q;
    const uint4* bBase = g_Wfrag + half * (16 * NKS * 32) + lane;

    #pragma unroll
    for (int ks = 0; ks < NKS; ks++) {
        const int ko = ks * 8;
        uint32_t a0h = aHi[ko],     a1h = aHi[ko + 8 * XROW_W];
        uint32_t a2h = aHi[ko + 4], a3h = aHi[ko + 4 + 8 * XROW_W];
        uint32_t a0l = aLo[ko],     a1l = aLo[ko + 8 * XROW_W];
        uint32_t a2l = aLo[ko + 4], a3l = aLo[ko + 4 + 8 * XROW_W];
        const uint4* bp = bBase + ks * 32;
        #pragma unroll
        for (int nt = 0; nt < 16; nt++) {
            uint4 b = __ldg(bp + nt * (NKS * 32));
            mma_bf16(acc[nt][0], acc[nt][1], acc[nt][2], acc[nt][3],
                     a0h, a1h, a2h, a3h, b.x, b.y);
            mma_bf16(acc[nt][0], acc[nt][1], acc[nt][2], acc[nt][3],
                     a0h, a1h, a2h, a3h, b.z, b.w);
            mma_bf16(acc[nt][0], acc[nt][1], acc[nt][2], acc[nt][3],
                     a0l, a1l, a2l, a3l, b.x, b.y);
        }
    }

    // Epilogue: bias + ReLU, row partial stats
    const float2* bb = reinterpret_cast<const float2*>(half ? b_neigh : b_self);
    float sA = 0.f, qA = 0.f, sB = 0.f, qB = 0.f;
    #pragma unroll
    for (int nt = 0; nt < 16; nt++) {
        float2 bv = __ldg(bb + nt * 4 + q);
        float v0 = fmaxf(acc[nt][0] + bv.x, 0.f);
        float v1 = fmaxf(acc[nt][1] + bv.y, 0.f);
        float v2 = fmaxf(acc[nt][2] + bv.x, 0.f);
        float v3 = fmaxf(acc[nt][3] + bv.y, 0.f);
        acc[nt][0] = v0; acc[nt][1] = v1; acc[nt][2] = v2; acc[nt][3] = v3;
        sA += v0 + v1;  qA += v0 * v0 + v1 * v1;
        sB += v2 + v3;  qB += v2 * v2 + v3 * v3;
    }
    #pragma unroll
    for (int o = 1; o <= 2; o <<= 1) {
        sA += __shfl_xor_sync(0xffffffffu, sA, o);
        qA += __shfl_xor_sync(0xffffffffu, qA, o);
        sB += __shfl_xor_sync(0xffffffffu, sB, o);
        qB += __shfl_xor_sync(0xffffffffu, qB, o);
    }
    if (q == 0) {
        sSum[half][mr + gr]     = sA;  sSq[half][mr + gr]     = qA;
        sSum[half][mr + gr + 8] = sB;  sSq[half][mr + gr + 8] = qB;
    }
    __syncthreads();

    int rowA = mr + gr, rowB = mr + gr + 8;
    float muA = (sSum[0][rowA] + sSum[1][rowA]) * (1.f / 256.f);
    float vaA = (sSq[0][rowA] + sSq[1][rowA]) * (1.f / 256.f) - muA * muA;
    float rsA = rsqrtf(vaA + LN_EPS);
    float muB = (sSum[0][rowB] + sSum[1][rowB]) * (1.f / 256.f);
    float vaB = (sSq[0][rowB] + sSq[1][rowB]) * (1.f / 256.f) - muB * muB;
    float rsB = rsqrtf(vaB + LN_EPS);

    const float2* gg = reinterpret_cast<const float2*>(gamma) + half * 64;
    const float2* ee = reinterpret_cast<const float2*>(beta)  + half * 64;
    int gnA = node0 + rowA;
    int gnB = node0 + rowB;
    #pragma unroll
    for (int nt = 0; nt < 16; nt++) {
        float2 gv = __ldg(gg + nt * 4 + q);
        float2 ev = __ldg(ee + nt * 4 + q);
        int coff = half * 128 + nt * 8 + 2 * q;
        if (gnA < NODES) {
            float2 o;
            o.x = (acc[nt][0] - muA) * rsA * gv.x + ev.x;
            o.y = (acc[nt][1] - muA) * rsA * gv.y + ev.y;
            *reinterpret_cast<float2*>(out + (size_t)gnA * DO2 + coff) = o;
        }
        if (gnB < NODES) {
            float2 o;
            o.x = (acc[nt][2] - muB) * rsB * gv.x + ev.x;
            o.y = (acc[nt][3] - muB) * rsB * gv.y + ev.y;
            *reinterpret_cast<float2*>(out + (size_t)gnB * DO2 + coff) = o;
        }
    }
}

// ---------------------------------------------------------------------------
extern "C" void kernel_launch(void* const* d_in, const int* in_sizes, int n_in,
                              void* d_out, int out_size) {
    const float* h        = (const float*)d_in[0];
    const int*   edge_row = (const int*)  d_in[1];
    const int*   edge_col = (const int*)  d_in[2];
    const float* edge_val = (const float*)d_in[3];
    const float* W_self   = (const float*)d_in[4];
    const float* b_self   = (const float*)d_in[5];
    const float* W_neigh  = (const float*)d_in[6];
    const float* b_neigh  = (const float*)d_in[7];
    const float* ln_gamma = (const float*)d_in[8];
    const float* ln_beta  = (const float*)d_in[9];
    float*       out      = (float*)d_out;

    const int E  = in_sizes[1];
    const int eb = (E + 255) / 256;

    static bool attr_done = false;
    if (!attr_done) {
        cudaFuncSetAttribute(gemm_ln_tc_kernel,
                             cudaFuncAttributeMaxDynamicSharedMemorySize, SMEM_GEMM);
        attr_done = true;
    }

    prep_kernel<<<(NODES * 32 + 255) / 256, 256>>>(h, W_self, W_neigh);
    scatter_kernel<<<eb, 256>>>(edge_row, edge_col, edge_val, E);
    spmm_kernel<<<(NODES * 32 + 255) / 256, 256>>>(h);
    gemm_ln_tc_kernel<<<GRID_G, 256, SMEM_GEMM>>>(b_self, b_neigh,
                                                  ln_gamma, ln_beta, out);
}

// round 13
// speedup vs baseline: 1.5867x; 1.3979x over previous
#include <cuda_runtime.h>
#include <cuda_bf16.h>
#include <cstdint>

#define D      128
#define DO2    256
#define NODES  50000
#define LN_EPS 1e-5f

#define CAP    64
#define SPILL_MAX 8192

#define MTILE  32
#define GRID_G ((NODES + MTILE - 1) / MTILE) // 1563

#define XROW_W 68
#define XT32_W (32 * XROW_W)            // 2176 words per tile
#define SMEM_GEMM (4 * XT32_W * 4)      // 34816 bytes

#define NKS    8

// Scratch
__device__ int      g_cnt[NODES];
__device__ int2     g_slots[NODES * CAP];
__device__ int4     g_spill[SPILL_MAX];
__device__ int      g_nspill;
// support in bf16 hi/lo packed form (written by spmm, L2-hot for gemm)
__device__ uint32_t g_shi[NODES * 64];
__device__ uint32_t g_slo[NODES * 64];
// W fragments, LDG.128-packed: uint4[half][nt(16)][ks(8)][lane(32)]
__device__ uint4    g_Wfrag[2 * 16 * NKS * 32];

// ---------------------------------------------------------------------------
__device__ __forceinline__ uint32_t pack_bf2(__nv_bfloat16 lo, __nv_bfloat16 hi) {
    return (uint32_t)__bfloat16_as_ushort(hi) << 16 | (uint32_t)__bfloat16_as_ushort(lo);
}

__device__ __forceinline__ void mma_bf16(float& d0, float& d1, float& d2, float& d3,
                                         uint32_t a0, uint32_t a1, uint32_t a2, uint32_t a3,
                                         uint32_t b0, uint32_t b1) {
    asm volatile(
        "mma.sync.aligned.m16n8k16.row.col.f32.bf16.bf16.f32 "
        "{%0,%1,%2,%3}, {%4,%5,%6,%7}, {%8,%9}, {%0,%1,%2,%3};"
        : "+f"(d0), "+f"(d1), "+f"(d2), "+f"(d3)
        : "r"(a0), "r"(a1), "r"(a2), "r"(a3), "r"(b0), "r"(b1));
}

__device__ __forceinline__ void split_packs(float4 x, uint2& hi, uint2& lo) {
    __nv_bfloat16 hx = __float2bfloat16_rn(x.x);
    __nv_bfloat16 hy = __float2bfloat16_rn(x.y);
    __nv_bfloat16 hz = __float2bfloat16_rn(x.z);
    __nv_bfloat16 hw = __float2bfloat16_rn(x.w);
    __nv_bfloat16 lx = __float2bfloat16_rn(x.x - __bfloat162float(hx));
    __nv_bfloat16 ly = __float2bfloat16_rn(x.y - __bfloat162float(hy));
    __nv_bfloat16 lz = __float2bfloat16_rn(x.z - __bfloat162float(hz));
    __nv_bfloat16 lw = __float2bfloat16_rn(x.w - __bfloat162float(hw));
    hi.x = pack_bf2(hx, hy);  hi.y = pack_bf2(hz, hw);
    lo.x = pack_bf2(lx, ly);  lo.y = pack_bf2(lz, lw);
}

// ---------------------------------------------------------------------------
// prep: zero counters + build packed bf16-split W fragments.
__global__ void prep_kernel(const float* __restrict__ Ws,
                            const float* __restrict__ Wn) {
    int idx = blockIdx.x * blockDim.x + threadIdx.x;
    if (idx < NODES) g_cnt[idx] = 0;
    if (idx == 0) g_nspill = 0;
    if (idx < 2 * 16 * NKS * 32 * 4) {
        int w    = idx & 3;
        int lane = (idx >> 2) & 31;
        int ks   = (idx >> 7) & 7;
        int nt   = (idx >> 10) & 15;
        int half = (idx >> 14) & 1;
        int p    = w >> 1;
        int reg  = w & 1;
        int n    = nt * 8 + (lane >> 2);
        int k    = ks * 16 + reg * 8 + 2 * (lane & 3);
        const float* W = half ? Wn : Ws;
        float w0 = W[n * D + k];
        float w1 = W[n * D + k + 1];
        __nv_bfloat16 h0 = __float2bfloat16_rn(w0);
        __nv_bfloat16 h1 = __float2bfloat16_rn(w1);
        __nv_bfloat16 v0, v1;
        if (p == 0) { v0 = h0; v1 = h1; }
        else {
            v0 = __float2bfloat16_rn(w0 - __bfloat162float(h0));
            v1 = __float2bfloat16_rn(w1 - __bfloat162float(h1));
        }
        reinterpret_cast<uint32_t*>(g_Wfrag)[idx] = pack_bf2(v0, v1);
    }
}

// ---------------------------------------------------------------------------
__global__ void scatter_kernel(const int*  __restrict__ row,
                               const int*  __restrict__ col,
                               const float* __restrict__ val,
                               int E) {
    int e = blockIdx.x * blockDim.x + threadIdx.x;
    if (e >= E) return;
    int r = row[e];
    int slot = atomicAdd(&g_cnt[r], 1);
    if (slot < CAP) {
        g_slots[r * CAP + slot] = make_int2(col[e], __float_as_int(val[e]));
    } else {
        int sp = atomicAdd(&g_nspill, 1);
        if (sp < SPILL_MAX)
            g_spill[sp] = make_int4(r, col[e], __float_as_int(val[e]), 0);
    }
}

// ---------------------------------------------------------------------------
// Bucketed SpMM: one warp per row; writes bf16-split packed support.
__global__ __launch_bounds__(256)
void spmm_kernel(const float* __restrict__ h) {
    int gw   = (blockIdx.x * blockDim.x + threadIdx.x) >> 5;
    int lane = threadIdx.x & 31;
    if (gw >= NODES) return;

    int cnt0 = g_cnt[gw];
    bool over = cnt0 > CAP;
    int cnt = over ? CAP : cnt0;
    int beg = gw * CAP;
    int end = beg + cnt;

    float4 acc = make_float4(0.f, 0.f, 0.f, 0.f);
    int  e  = beg;
    int2 cv = (e < end) ? __ldg(&g_slots[e]) : make_int2(0, 0);
    while (e < end) {
        int2 cur = cv;
        if (e + 1 < end) cv = __ldg(&g_slots[e + 1]);
        float  v = __int_as_float(cur.y);
        float4 x = __ldg(reinterpret_cast<const float4*>(h + (size_t)cur.x * D) + lane);
        acc.x = fmaf(v, x.x, acc.x);
        acc.y = fmaf(v, x.y, acc.y);
        acc.z = fmaf(v, x.z, acc.z);
        acc.w = fmaf(v, x.w, acc.w);
        e++;
    }
    if (over) {
        int n = g_nspill; if (n > SPILL_MAX) n = SPILL_MAX;
        for (int i = 0; i < n; i++) {
            int4 s = g_spill[i];
            if (s.x == gw) {
                float v = __int_as_float(s.z);
                float4 x = __ldg(reinterpret_cast<const float4*>(h + (size_t)s.y * D) + lane);
                acc.x = fmaf(v, x.x, acc.x);
                acc.y = fmaf(v, x.y, acc.y);
                acc.z = fmaf(v, x.z, acc.z);
                acc.w = fmaf(v, x.w, acc.w);
            }
        }
    }
    uint2 hi, lo;
    split_packs(acc, hi, lo);
    reinterpret_cast<uint2*>(g_shi)[gw * 32 + lane] = hi;
    reinterpret_cast<uint2*>(g_slo)[gw * 32 + lane] = lo;
}

// ---------------------------------------------------------------------------
// Tensor-core fused GEMM (bf16x3 split via mma.sync) + concat + ReLU + LN.
// 32 nodes/CTA, 8 warps. Warp: mgrp=wid>>2 (rows 16*mgrp..+16),
// half=(wid>>1)&1, ntb=(wid&1)*8 (8 n-tiles = 64 cols of its half).
__global__ __launch_bounds__(256, 3)
void gemm_ln_tc_kernel(const float* __restrict__ h,
                       const float* __restrict__ b_self,
                       const float* __restrict__ b_neigh,
                       const float* __restrict__ gamma,
                       const float* __restrict__ beta,
                       float* __restrict__ out) {
    extern __shared__ uint32_t sX[];        // tiles: 0=h_hi 1=h_lo 2=s_hi 3=s_lo
    __shared__ float sSum[4][32];           // [half*2+ntbI][row]
    __shared__ float sSq[4][32];
    __shared__ float sMu[32], sRs[32];

    const int tid   = threadIdx.x;
    const int node0 = blockIdx.x * MTILE;

    // Stage h (fp32, L2-hot) -> bf16 hi/lo tiles. 1024 float4, 4/thread.
    #pragma unroll
    for (int it = 0; it < 4; it++) {
        int i   = tid + it * 256;
        int row = i >> 5, q4 = i & 31;
        int gn  = node0 + row;
        float4 x = (gn < NODES)
                 ? __ldg(reinterpret_cast<const float4*>(h + (size_t)gn * D) + q4)
                 : make_float4(0.f, 0.f, 0.f, 0.f);
        uint2 hi, lo;
        split_packs(x, hi, lo);
        *reinterpret_cast<uint2*>(sX + 0 * XT32_W + row * XROW_W + 2 * q4) = hi;
        *reinterpret_cast<uint2*>(sX + 1 * XT32_W + row * XROW_W + 2 * q4) = lo;
    }
    // Stage support (pre-split, L2-hot) -> pure uint4 copies. 1024, 4/thread.
    #pragma unroll
    for (int it = 0; it < 4; it++) {
        int i    = tid + it * 256;
        int tile = i >> 9;          // 0..1
        int rem  = i & 511;
        int row  = rem >> 4, u4 = rem & 15;
        int gn   = node0 + row;
        uint4 v = make_uint4(0u, 0u, 0u, 0u);
        if (gn < NODES)
            v = __ldg(reinterpret_cast<const uint4*>(tile ? g_slo : g_shi) + gn * 16 + u4);
        *reinterpret_cast<uint4*>(sX + (2 + tile) * XT32_W + row * XROW_W + u4 * 4) = v;
    }
    __syncthreads();

    const int wid  = tid >> 5;
    const int lane = tid & 31;
    const int mgrp = wid >> 2;
    const int half = (wid >> 1) & 1;
    const int ntbI = wid & 1;
    const int ntb  = ntbI * 8;
    const int mr   = mgrp * 16;
    const int gr   = lane >> 2;
    const int q    = lane & 3;

    float acc[8][4];
    #pragma unroll
    for (int nt = 0; nt < 8; nt++)
        acc[nt][0] = acc[nt][1] = acc[nt][2] = acc[nt][3] = 0.f;

    const uint32_t* aHi = sX + (half * 2 + 0) * XT32_W + (mr + gr) * XROW_W + q;
    const uint32_t* aLo = sX + (half * 2 + 1) * XT32_W + (mr + gr) * XROW_W + q;
    const uint4* bBase = g_Wfrag + half * (16 * NKS * 32) + ntb * (NKS * 32) + lane;

    #pragma unroll
    for (int ks = 0; ks < NKS; ks++) {
        const int ko = ks * 8;
        uint32_t a0h = aHi[ko],     a1h = aHi[ko + 8 * XROW_W];
        uint32_t a2h = aHi[ko + 4], a3h = aHi[ko + 4 + 8 * XROW_W];
        uint32_t a0l = aLo[ko],     a1l = aLo[ko + 8 * XROW_W];
        uint32_t a2l = aLo[ko + 4], a3l = aLo[ko + 4 + 8 * XROW_W];
        const uint4* bp = bBase + ks * 32;
        #pragma unroll
        for (int nt = 0; nt < 8; nt++) {
            uint4 b = __ldg(bp + nt * (NKS * 32));
            mma_bf16(acc[nt][0], acc[nt][1], acc[nt][2], acc[nt][3],
                     a0h, a1h, a2h, a3h, b.x, b.y);
            mma_bf16(acc[nt][0], acc[nt][1], acc[nt][2], acc[nt][3],
                     a0h, a1h, a2h, a3h, b.z, b.w);
            mma_bf16(acc[nt][0], acc[nt][1], acc[nt][2], acc[nt][3],
                     a0l, a1l, a2l, a3l, b.x, b.y);
        }
    }

    // Epilogue: bias + ReLU, row partial stats
    const float2* bb = reinterpret_cast<const float2*>(half ? b_neigh : b_self);
    float sA = 0.f, qA = 0.f, sB = 0.f, qB = 0.f;
    #pragma unroll
    for (int nt = 0; nt < 8; nt++) {
        float2 bv = __ldg(bb + (ntb + nt) * 4 + q);
        float v0 = fmaxf(acc[nt][0] + bv.x, 0.f);
        float v1 = fmaxf(acc[nt][1] + bv.y, 0.f);
        float v2 = fmaxf(acc[nt][2] + bv.x, 0.f);
        float v3 = fmaxf(acc[nt][3] + bv.y, 0.f);
        acc[nt][0] = v0; acc[nt][1] = v1; acc[nt][2] = v2; acc[nt][3] = v3;
        sA += v0 + v1;  qA += v0 * v0 + v1 * v1;
        sB += v2 + v3;  qB += v2 * v2 + v3 * v3;
    }
    #pragma unroll
    for (int o = 1; o <= 2; o <<= 1) {
        sA += __shfl_xor_sync(0xffffffffu, sA, o);
        qA += __shfl_xor_sync(0xffffffffu, qA, o);
        sB += __shfl_xor_sync(0xffffffffu, sB, o);
        qB += __shfl_xor_sync(0xffffffffu, qB, o);
    }
    if (q == 0) {
        sSum[half * 2 + ntbI][mr + gr]     = sA;  sSq[half * 2 + ntbI][mr + gr]     = qA;
        sSum[half * 2 + ntbI][mr + gr + 8] = sB;  sSq[half * 2 + ntbI][mr + gr + 8] = qB;
    }
    __syncthreads();

    if (tid < 32) {
        float s  = sSum[0][tid] + sSum[1][tid] + sSum[2][tid] + sSum[3][tid];
        float sq = sSq[0][tid] + sSq[1][tid] + sSq[2][tid] + sSq[3][tid];
        float mu  = s * (1.f / 256.f);
        float var = sq * (1.f / 256.f) - mu * mu;
        sMu[tid] = mu;
        sRs[tid] = rsqrtf(var + LN_EPS);
    }
    __syncthreads();

    int rowA = mr + gr, rowB = mr + gr + 8;
    float muA = sMu[rowA], rsA = sRs[rowA];
    float muB = sMu[rowB], rsB = sRs[rowB];
    int gnA = node0 + rowA;
    int gnB = node0 + rowB;

    const float2* gg = reinterpret_cast<const float2*>(gamma) + half * 64;
    const float2* ee = reinterpret_cast<const float2*>(beta)  + half * 64;
    #pragma unroll
    for (int nt = 0; nt < 8; nt++) {
        float2 gv = __ldg(gg + (ntb + nt) * 4 + q);
        float2 ev = __ldg(ee + (ntb + nt) * 4 + q);
        int coff = half * 128 + (ntb + nt) * 8 + 2 * q;
        if (gnA < NODES) {
            float2 o;
            o.x = (acc[nt][0] - muA) * rsA * gv.x + ev.x;
            o.y = (acc[nt][1] - muA) * rsA * gv.y + ev.y;
            *reinterpret_cast<float2*>(out + (size_t)gnA * DO2 + coff) = o;
        }
        if (gnB < NODES) {
            float2 o;
            o.x = (acc[nt][2] - muB) * rsB * gv.x + ev.x;
            o.y = (acc[nt][3] - muB) * rsB * gv.y + ev.y;
            *reinterpret_cast<float2*>(out + (size_t)gnB * DO2 + coff) = o;
        }
    }
}

// ---------------------------------------------------------------------------
extern "C" void kernel_launch(void* const* d_in, const int* in_sizes, int n_in,
                              void* d_out, int out_size) {
    const float* h        = (const float*)d_in[0];
    const int*   edge_row = (const int*)  d_in[1];
    const int*   edge_col = (const int*)  d_in[2];
    const float* edge_val = (const float*)d_in[3];
    const float* W_self   = (const float*)d_in[4];
    const float* b_self   = (const float*)d_in[5];
    const float* W_neigh  = (const float*)d_in[6];
    const float* b_neigh  = (const float*)d_in[7];
    const float* ln_gamma = (const float*)d_in[8];
    const float* ln_beta  = (const float*)d_in[9];
    float*       out      = (float*)d_out;

    const int E  = in_sizes[1];
    const int eb = (E + 255) / 256;

    static bool attr_done = false;
    if (!attr_done) {
        cudaFuncSetAttribute(gemm_ln_tc_kernel,
                             cudaFuncAttributeMaxDynamicSharedMemorySize, SMEM_GEMM);
        attr_done = true;
    }

    prep_kernel<<<196, 256>>>(W_self, W_neigh);
    scatter_kernel<<<eb, 256>>>(edge_row, edge_col, edge_val, E);
    spmm_kernel<<<(NODES * 32 + 255) / 256, 256>>>(h);
    gemm_ln_tc_kernel<<<GRID_G, 256, SMEM_GEMM>>>(h, b_self, b_neigh,
                                                  ln_gamma, ln_beta, out);
}

// round 14
// speedup vs baseline: 1.6299x; 1.0273x over previous
#include <cuda_runtime.h>
#include <cuda_bf16.h>
#include <cstdint>

#define D      128
#define DO2    256
#define NODES  50000
#define LN_EPS 1e-5f

#define CAP    64
#define SPILL_MAX 8192

#define MTILE  64
#define GRID_G ((NODES + MTILE - 1) / MTILE) // 782

#define XROW_W 68
#define XT64_W (64 * XROW_W)            // 4352 words per tile
#define SMEM_GEMM (4 * XT64_W * 4)      // 69632 bytes

#define NKS    8

// Scratch
__device__ int      g_cnt[NODES];
__device__ int2     g_slots[NODES * CAP];
__device__ int4     g_spill[SPILL_MAX];
__device__ int      g_nspill;
// support in bf16 hi/lo packed form (written by spmm, L2-hot for gemm)
__device__ uint32_t g_shi[NODES * 64];
__device__ uint32_t g_slo[NODES * 64];
// W fragments, LDG.128-packed: uint4[half][nt(16)][ks(8)][lane(32)]
__device__ uint4    g_Wfrag[2 * 16 * NKS * 32];

// ---------------------------------------------------------------------------
__device__ __forceinline__ uint32_t pack_bf2(__nv_bfloat16 lo, __nv_bfloat16 hi) {
    return (uint32_t)__bfloat16_as_ushort(hi) << 16 | (uint32_t)__bfloat16_as_ushort(lo);
}

__device__ __forceinline__ void mma_bf16(float& d0, float& d1, float& d2, float& d3,
                                         uint32_t a0, uint32_t a1, uint32_t a2, uint32_t a3,
                                         uint32_t b0, uint32_t b1) {
    asm volatile(
        "mma.sync.aligned.m16n8k16.row.col.f32.bf16.bf16.f32 "
        "{%0,%1,%2,%3}, {%4,%5,%6,%7}, {%8,%9}, {%0,%1,%2,%3};"
        : "+f"(d0), "+f"(d1), "+f"(d2), "+f"(d3)
        : "r"(a0), "r"(a1), "r"(a2), "r"(a3), "r"(b0), "r"(b1));
}

__device__ __forceinline__ void split_packs(float4 x, uint2& hi, uint2& lo) {
    __nv_bfloat16 hx = __float2bfloat16_rn(x.x);
    __nv_bfloat16 hy = __float2bfloat16_rn(x.y);
    __nv_bfloat16 hz = __float2bfloat16_rn(x.z);
    __nv_bfloat16 hw = __float2bfloat16_rn(x.w);
    __nv_bfloat16 lx = __float2bfloat16_rn(x.x - __bfloat162float(hx));
    __nv_bfloat16 ly = __float2bfloat16_rn(x.y - __bfloat162float(hy));
    __nv_bfloat16 lz = __float2bfloat16_rn(x.z - __bfloat162float(hz));
    __nv_bfloat16 lw = __float2bfloat16_rn(x.w - __bfloat162float(hw));
    hi.x = pack_bf2(hx, hy);  hi.y = pack_bf2(hz, hw);
    lo.x = pack_bf2(lx, ly);  lo.y = pack_bf2(lz, lw);
}

// ---------------------------------------------------------------------------
// prep: zero counters + build packed bf16-split W fragments.
__global__ void prep_kernel(const float* __restrict__ Ws,
                            const float* __restrict__ Wn) {
    int idx = blockIdx.x * blockDim.x + threadIdx.x;
    if (idx < NODES) g_cnt[idx] = 0;
    if (idx == 0) g_nspill = 0;
    if (idx < 2 * 16 * NKS * 32 * 4) {
        int w    = idx & 3;
        int lane = (idx >> 2) & 31;
        int ks   = (idx >> 7) & 7;
        int nt   = (idx >> 10) & 15;
        int half = (idx >> 14) & 1;
        int p    = w >> 1;
        int reg  = w & 1;
        int n    = nt * 8 + (lane >> 2);
        int k    = ks * 16 + reg * 8 + 2 * (lane & 3);
        const float* W = half ? Wn : Ws;
        float w0 = W[n * D + k];
        float w1 = W[n * D + k + 1];
        __nv_bfloat16 h0 = __float2bfloat16_rn(w0);
        __nv_bfloat16 h1 = __float2bfloat16_rn(w1);
        __nv_bfloat16 v0, v1;
        if (p == 0) { v0 = h0; v1 = h1; }
        else {
            v0 = __float2bfloat16_rn(w0 - __bfloat162float(h0));
            v1 = __float2bfloat16_rn(w1 - __bfloat162float(h1));
        }
        reinterpret_cast<uint32_t*>(g_Wfrag)[idx] = pack_bf2(v0, v1);
    }
}

// ---------------------------------------------------------------------------
__global__ void scatter_kernel(const int*  __restrict__ row,
                               const int*  __restrict__ col,
                               const float* __restrict__ val,
                               int E) {
    int e = blockIdx.x * blockDim.x + threadIdx.x;
    if (e >= E) return;
    int r = row[e];
    int slot = atomicAdd(&g_cnt[r], 1);
    if (slot < CAP) {
        g_slots[r * CAP + slot] = make_int2(col[e], __float_as_int(val[e]));
    } else {
        int sp = atomicAdd(&g_nspill, 1);
        if (sp < SPILL_MAX)
            g_spill[sp] = make_int4(r, col[e], __float_as_int(val[e]), 0);
    }
}

// ---------------------------------------------------------------------------
// Bucketed SpMM: one warp per row; writes bf16-split packed support.
__global__ __launch_bounds__(256)
void spmm_kernel(const float* __restrict__ h) {
    int gw   = (blockIdx.x * blockDim.x + threadIdx.x) >> 5;
    int lane = threadIdx.x & 31;
    if (gw >= NODES) return;

    int cnt0 = g_cnt[gw];
    bool over = cnt0 > CAP;
    int cnt = over ? CAP : cnt0;
    int beg = gw * CAP;
    int end = beg + cnt;

    float4 acc = make_float4(0.f, 0.f, 0.f, 0.f);
    int  e  = beg;
    int2 cv = (e < end) ? __ldg(&g_slots[e]) : make_int2(0, 0);
    while (e < end) {
        int2 cur = cv;
        if (e + 1 < end) cv = __ldg(&g_slots[e + 1]);
        float  v = __int_as_float(cur.y);
        float4 x = __ldg(reinterpret_cast<const float4*>(h + (size_t)cur.x * D) + lane);
        acc.x = fmaf(v, x.x, acc.x);
        acc.y = fmaf(v, x.y, acc.y);
        acc.z = fmaf(v, x.z, acc.z);
        acc.w = fmaf(v, x.w, acc.w);
        e++;
    }
    if (over) {
        int n = g_nspill; if (n > SPILL_MAX) n = SPILL_MAX;
        for (int i = 0; i < n; i++) {
            int4 s = g_spill[i];
            if (s.x == gw) {
                float v = __int_as_float(s.z);
                float4 x = __ldg(reinterpret_cast<const float4*>(h + (size_t)s.y * D) + lane);
                acc.x = fmaf(v, x.x, acc.x);
                acc.y = fmaf(v, x.y, acc.y);
                acc.z = fmaf(v, x.z, acc.z);
                acc.w = fmaf(v, x.w, acc.w);
            }
        }
    }
    uint2 hi, lo;
    split_packs(acc, hi, lo);
    reinterpret_cast<uint2*>(g_shi)[gw * 32 + lane] = hi;
    reinterpret_cast<uint2*>(g_slo)[gw * 32 + lane] = lo;
}

// ---------------------------------------------------------------------------
// Tensor-core fused GEMM (bf16x3 split via mma.sync) + concat + ReLU + LN.
// 64 nodes/CTA, 8 warps. Warp: half=wid>>2, ntbI=(wid>>1)&1 (8 n-tiles),
// mgp=wid&1 (rows mgp*32 .. +32 = 2 m-groups). Each B fragment is loaded
// once and used by 6 HMMAs (2 m-groups x 3 split terms) -> half the B L1
// traffic of the 32-node version.
__global__ __launch_bounds__(256, 2)
void gemm_ln_tc_kernel(const float* __restrict__ h,
                       const float* __restrict__ b_self,
                       const float* __restrict__ b_neigh,
                       const float* __restrict__ gamma,
                       const float* __restrict__ beta,
                       float* __restrict__ out) {
    extern __shared__ uint32_t sX[];        // tiles: 0=h_hi 1=h_lo 2=s_hi 3=s_lo
    __shared__ float sSum[4][64];           // [half*2+ntbI][row]
    __shared__ float sSq[4][64];
    __shared__ float sMu[64], sRs[64];

    const int tid   = threadIdx.x;
    const int node0 = blockIdx.x * MTILE;

    // Stage h (fp32, L2-hot) -> bf16 hi/lo tiles. 2048 float4, 8/thread.
    #pragma unroll
    for (int it = 0; it < 8; it++) {
        int i   = tid + it * 256;
        int row = i >> 5, q4 = i & 31;
        int gn  = node0 + row;
        float4 x = (gn < NODES)
                 ? __ldg(reinterpret_cast<const float4*>(h + (size_t)gn * D) + q4)
                 : make_float4(0.f, 0.f, 0.f, 0.f);
        uint2 hi, lo;
        split_packs(x, hi, lo);
        *reinterpret_cast<uint2*>(sX + 0 * XT64_W + row * XROW_W + 2 * q4) = hi;
        *reinterpret_cast<uint2*>(sX + 1 * XT64_W + row * XROW_W + 2 * q4) = lo;
    }
    // Stage support (pre-split, L2-hot) -> pure uint4 copies. 2048, 8/thread.
    #pragma unroll
    for (int it = 0; it < 8; it++) {
        int i    = tid + it * 256;
        int tile = i >> 10;         // 0..1
        int rem  = i & 1023;
        int row  = rem >> 4, u4 = rem & 15;
        int gn   = node0 + row;
        uint4 v = make_uint4(0u, 0u, 0u, 0u);
        if (gn < NODES)
            v = __ldg(reinterpret_cast<const uint4*>(tile ? g_slo : g_shi) + gn * 16 + u4);
        *reinterpret_cast<uint4*>(sX + (2 + tile) * XT64_W + row * XROW_W + u4 * 4) = v;
    }
    __syncthreads();

    const int wid  = tid >> 5;
    const int lane = tid & 31;
    const int half = wid >> 2;
    const int ntbI = (wid >> 1) & 1;
    const int ntb  = ntbI * 8;
    const int mgp  = wid & 1;
    const int mr0  = mgp * 32;          // m-group 0: rows mr0..mr0+15, mg1: +16
    const int gr   = lane >> 2;
    const int q    = lane & 3;

    float acc[2][8][4];
    #pragma unroll
    for (int mg = 0; mg < 2; mg++)
        #pragma unroll
        for (int nt = 0; nt < 8; nt++)
            acc[mg][nt][0] = acc[mg][nt][1] = acc[mg][nt][2] = acc[mg][nt][3] = 0.f;

    const uint32_t* aHi0 = sX + (half * 2 + 0) * XT64_W + (mr0 + gr) * XROW_W + q;
    const uint32_t* aLo0 = sX + (half * 2 + 1) * XT64_W + (mr0 + gr) * XROW_W + q;
    const uint32_t* aHi1 = aHi0 + 16 * XROW_W;
    const uint32_t* aLo1 = aLo0 + 16 * XROW_W;
    const uint4* bBase = g_Wfrag + half * (16 * NKS * 32) + ntb * (NKS * 32) + lane;

    #pragma unroll
    for (int ks = 0; ks < NKS; ks++) {
        const int ko = ks * 8;
        uint32_t a0h0 = aHi0[ko],     a1h0 = aHi0[ko + 8 * XROW_W];
        uint32_t a2h0 = aHi0[ko + 4], a3h0 = aHi0[ko + 4 + 8 * XROW_W];
        uint32_t a0l0 = aLo0[ko],     a1l0 = aLo0[ko + 8 * XROW_W];
        uint32_t a2l0 = aLo0[ko + 4], a3l0 = aLo0[ko + 4 + 8 * XROW_W];
        uint32_t a0h1 = aHi1[ko],     a1h1 = aHi1[ko + 8 * XROW_W];
        uint32_t a2h1 = aHi1[ko + 4], a3h1 = aHi1[ko + 4 + 8 * XROW_W];
        uint32_t a0l1 = aLo1[ko],     a1l1 = aLo1[ko + 8 * XROW_W];
        uint32_t a2l1 = aLo1[ko + 4], a3l1 = aLo1[ko + 4 + 8 * XROW_W];
        const uint4* bp = bBase + ks * 32;
        #pragma unroll
        for (int nt = 0; nt < 8; nt++) {
            uint4 b = __ldg(bp + nt * (NKS * 32));
            mma_bf16(acc[0][nt][0], acc[0][nt][1], acc[0][nt][2], acc[0][nt][3],
                     a0h0, a1h0, a2h0, a3h0, b.x, b.y);
            mma_bf16(acc[0][nt][0], acc[0][nt][1], acc[0][nt][2], acc[0][nt][3],
                     a0h0, a1h0, a2h0, a3h0, b.z, b.w);
            mma_bf16(acc[0][nt][0], acc[0][nt][1], acc[0][nt][2], acc[0][nt][3],
                     a0l0, a1l0, a2l0, a3l0, b.x, b.y);
            mma_bf16(acc[1][nt][0], acc[1][nt][1], acc[1][nt][2], acc[1][nt][3],
                     a0h1, a1h1, a2h1, a3h1, b.x, b.y);
            mma_bf16(acc[1][nt][0], acc[1][nt][1], acc[1][nt][2], acc[1][nt][3],
                     a0h1, a1h1, a2h1, a3h1, b.z, b.w);
            mma_bf16(acc[1][nt][0], acc[1][nt][1], acc[1][nt][2], acc[1][nt][3],
                     a0l1, a1l1, a2l1, a3l1, b.x, b.y);
        }
    }

    // Epilogue: bias + ReLU, row partial stats (per m-group)
    const float2* bb = reinterpret_cast<const float2*>(half ? b_neigh : b_self);
    #pragma unroll
    for (int mg = 0; mg < 2; mg++) {
        float sA = 0.f, qA = 0.f, sB = 0.f, qB = 0.f;
        #pragma unroll
        for (int nt = 0; nt < 8; nt++) {
            float2 bv = __ldg(bb + (ntb + nt) * 4 + q);
            float v0 = fmaxf(acc[mg][nt][0] + bv.x, 0.f);
            float v1 = fmaxf(acc[mg][nt][1] + bv.y, 0.f);
            float v2 = fmaxf(acc[mg][nt][2] + bv.x, 0.f);
            float v3 = fmaxf(acc[mg][nt][3] + bv.y, 0.f);
            acc[mg][nt][0] = v0; acc[mg][nt][1] = v1;
            acc[mg][nt][2] = v2; acc[mg][nt][3] = v3;
            sA += v0 + v1;  qA += v0 * v0 + v1 * v1;
            sB += v2 + v3;  qB += v2 * v2 + v3 * v3;
        }
        #pragma unroll
        for (int o = 1; o <= 2; o <<= 1) {
            sA += __shfl_xor_sync(0xffffffffu, sA, o);
            qA += __shfl_xor_sync(0xffffffffu, qA, o);
            sB += __shfl_xor_sync(0xffffffffu, sB, o);
            qB += __shfl_xor_sync(0xffffffffu, qB, o);
        }
        if (q == 0) {
            int r0 = mr0 + mg * 16 + gr;
            sSum[half * 2 + ntbI][r0]     = sA;  sSq[half * 2 + ntbI][r0]     = qA;
            sSum[half * 2 + ntbI][r0 + 8] = sB;  sSq[half * 2 + ntbI][r0 + 8] = qB;
        }
    }
    __syncthreads();

    if (tid < 64) {
        float s  = sSum[0][tid] + sSum[1][tid] + sSum[2][tid] + sSum[3][tid];
        float sq = sSq[0][tid] + sSq[1][tid] + sSq[2][tid] + sSq[3][tid];
        float mu  = s * (1.f / 256.f);
        float var = sq * (1.f / 256.f) - mu * mu;
        sMu[tid] = mu;
        sRs[tid] = rsqrtf(var + LN_EPS);
    }
    __syncthreads();

    const float2* gg = reinterpret_cast<const float2*>(gamma) + half * 64;
    const float2* ee = reinterpret_cast<const float2*>(beta)  + half * 64;
    #pragma unroll
    for (int mg = 0; mg < 2; mg++) {
        int rowA = mr0 + mg * 16 + gr;
        int rowB = rowA + 8;
        float muA = sMu[rowA], rsA = sRs[rowA];
        float muB = sMu[rowB], rsB = sRs[rowB];
        int gnA = node0 + rowA;
        int gnB = node0 + rowB;
        #pragma unroll
        for (int nt = 0; nt < 8; nt++) {
            float2 gv = __ldg(gg + (ntb + nt) * 4 + q);
            float2 ev = __ldg(ee + (ntb + nt) * 4 + q);
            int coff = half * 128 + (ntb + nt) * 8 + 2 * q;
            if (gnA < NODES) {
                float2 o;
                o.x = (acc[mg][nt][0] - muA) * rsA * gv.x + ev.x;
                o.y = (acc[mg][nt][1] - muA) * rsA * gv.y + ev.y;
                *reinterpret_cast<float2*>(out + (size_t)gnA * DO2 + coff) = o;
            }
            if (gnB < NODES) {
                float2 o;
                o.x = (acc[mg][nt][2] - muB) * rsB * gv.x + ev.x;
                o.y = (acc[mg][nt][3] - muB) * rsB * gv.y + ev.y;
                *reinterpret_cast<float2*>(out + (size_t)gnB * DO2 + coff) = o;
            }
        }
    }
}

// ---------------------------------------------------------------------------
extern "C" void kernel_launch(void* const* d_in, const int* in_sizes, int n_in,
                              void* d_out, int out_size) {
    const float* h        = (const float*)d_in[0];
    const int*   edge_row = (const int*)  d_in[1];
    const int*   edge_col = (const int*)  d_in[2];
    const float* edge_val = (const float*)d_in[3];
    const float* W_self   = (const float*)d_in[4];
    const float* b_self   = (const float*)d_in[5];
    const float* W_neigh  = (const float*)d_in[6];
    const float* b_neigh  = (const float*)d_in[7];
    const float* ln_gamma = (const float*)d_in[8];
    const float* ln_beta  = (const float*)d_in[9];
    float*       out      = (float*)d_out;

    const int E  = in_sizes[1];
    const int eb = (E + 255) / 256;

    static bool attr_done = false;
    if (!attr_done) {
        cudaFuncSetAttribute(gemm_ln_tc_kernel,
                             cudaFuncAttributeMaxDynamicSharedMemorySize, SMEM_GEMM);
        attr_done = true;
    }

    prep_kernel<<<196, 256>>>(W_self, W_neigh);
    scatter_kernel<<<eb, 256>>>(edge_row, edge_col, edge_val, E);
    spmm_kernel<<<(NODES * 32 + 255) / 256, 256>>>(h);
    gemm_ln_tc_kernel<<<GRID_G, 256, SMEM_GEMM>>>(h, b_self, b_neigh,
                                                  ln_gamma, ln_beta, out);
}